// round 12
// baseline (speedup 1.0000x reference)
#include <cuda_runtime.h>
#include <cuda_bf16.h>
#include <math.h>
#include <stdint.h>

// Problem constants
#define BB 4
#define SS 4096
#define DD 1024
#define HH 8
#define KK 128
#define PP 32
#define NROW (BB*SS)          // 16384
#define PI_F 3.14159265358979f

// ---------------------------------------------------------------------------
// Device-global scratch (no allocations allowed)
// ---------------------------------------------------------------------------
__device__ __nv_bfloat16 g_xh[(size_t)NROW * DD];   // bf16 hi of x
__device__ __nv_bfloat16 g_xl[(size_t)NROW * DD];   // bf16 lo of x
__device__ __nv_bfloat16 g_mh[(size_t)NROW * DD];   // bf16 hi of mixed
__device__ __nv_bfloat16 g_ml[(size_t)NROW * DD];   // bf16 lo of mixed
__device__ __nv_bfloat16 g_wh1[DD * DD], g_wl1[DD * DD];  // W_proj hi/lo
__device__ __nv_bfloat16 g_wh2[DD * DD], g_wl2[DD * DD];  // out_W hi/lo
__device__ float g_heads[(size_t)NROW * DD];        // heads fp32, later y
__device__ float g_part[64 * DD];                   // per-row-tile column sums
__device__ float g_coef[BB * HH * HH];              // 0.1/(1+imp), zero diag

__device__ __forceinline__ uint32_t smem_to_u32(const void* smem_ptr) {
    uint32_t addr;
    asm("{ .reg .u64 tmp; cvta.to.shared.u64 tmp, %1; cvt.u32.u64 %0, tmp; }"
        : "=r"(addr) : "l"(smem_ptr));
    return addr;
}

__device__ __forceinline__ void cpasync16(uint32_t dst, const void* src) {
    asm volatile("cp.async.cg.shared.global [%0], [%1], 16;"
                 :: "r"(dst), "l"(src) : "memory");
}

#define CP_COMMIT() asm volatile("cp.async.commit_group;" ::: "memory")
#define CP_WAIT1()  asm volatile("cp.async.wait_group 1;" ::: "memory")

#define LDSM4(r, addr) \
    asm volatile("ldmatrix.sync.aligned.m8n8.x4.shared.b16 {%0,%1,%2,%3}, [%4];" \
        : "=r"((r)[0]), "=r"((r)[1]), "=r"((r)[2]), "=r"((r)[3]) : "r"(addr))

__device__ __forceinline__ void mma_bf16(float* c, const uint32_t* a,
                                         uint32_t b0, uint32_t b1) {
    asm volatile(
        "mma.sync.aligned.m16n8k16.row.col.f32.bf16.bf16.f32 "
        "{%0,%1,%2,%3}, {%4,%5,%6,%7}, {%8,%9}, {%0,%1,%2,%3};"
        : "+f"(c[0]), "+f"(c[1]), "+f"(c[2]), "+f"(c[3])
        : "r"(a[0]), "r"(a[1]), "r"(a[2]), "r"(a[3]), "r"(b0), "r"(b1));
}

// ---------------------------------------------------------------------------
// bf16 hi/lo split conversion: all three tensors in ONE launch.
// ---------------------------------------------------------------------------
#define NBX (NROW * DD / 4 / 256)   // 4096 blocks for x
#define NBW (DD * DD / 4 / 256)     // 1024 blocks per weight
__global__ void convert_split_all(const float* __restrict__ x,
                                  const float* __restrict__ w1,
                                  const float* __restrict__ w2)
{
    int blk = blockIdx.x;
    const float* src;
    __nv_bfloat16 *hp, *lp;
    int i;
    if (blk < NBX) {
        src = x;  hp = g_xh;  lp = g_xl;
        i = blk * 256 + threadIdx.x;
    } else if (blk < NBX + NBW) {
        src = w1; hp = g_wh1; lp = g_wl1;
        i = (blk - NBX) * 256 + threadIdx.x;
    } else {
        src = w2; hp = g_wh2; lp = g_wl2;
        i = (blk - NBX - NBW) * 256 + threadIdx.x;
    }
    float4 v = ((const float4*)src)[i];
    __nv_bfloat162 h01 = __floats2bfloat162_rn(v.x, v.y);
    __nv_bfloat162 h23 = __floats2bfloat162_rn(v.z, v.w);
    __nv_bfloat162 l01 = __floats2bfloat162_rn(v.x - __low2float(h01),
                                               v.y - __high2float(h01));
    __nv_bfloat162 l23 = __floats2bfloat162_rn(v.z - __low2float(h23),
                                               v.w - __high2float(h23));
    ((__nv_bfloat162*)hp)[2 * i + 0] = h01;
    ((__nv_bfloat162*)hp)[2 * i + 1] = h23;
    ((__nv_bfloat162*)lp)[2 * i + 0] = l01;
    ((__nv_bfloat162*)lp)[2 * i + 1] = l23;
}

// ---------------------------------------------------------------------------
// mma.sync GEMM: C[n,m] = sum_d A[n,d]*W[m,d] via 3xbf16 split.
// CTA tile 256(M)x128(N), BK=32, 256 threads (8 warps, 4 wm x 2 wn, warp
// 64x64), 2-stage cp.async pipeline, 1 CTA/SM.  R7 inner ordering.
//   MODE 0: A = x(hi/lo),   epi: * cos(freq[m]*pi) -> g_heads, + colsum->g_part
//   MODE 1: A = mixed(hi/lo), epi: + out_b[m] + x[n,m]        -> g_heads
// SMEM rows padded to 80B -> conflict-free ldmatrix phases.
// ---------------------------------------------------------------------------
#define RSB   80                 // row stride bytes (32 bf16 + 16B pad)
#define AOPB  (256 * RSB)        // 20480 bytes per A operand tile
#define BOPB  (128 * RSB)        // 10240 bytes per B operand tile
#define STGB  (2 * AOPB + 2 * BOPB)  // 61440 per stage (Ah|Al|Bh|Bl)
#define NSTG  2
#define GEMM_SMEM (NSTG * STGB)  // 122880

template<int MODE>
__global__ __launch_bounds__(256, 1)
void gemm_mma(const float* __restrict__ xres, const float* __restrict__ aux)
{
    extern __shared__ char sm[];
    const uint32_t sb = smem_to_u32(sm);
    const int tid = threadIdx.x;
    const int lane = tid & 31;
    const int wid = tid >> 5;        // 0..7
    const int wm = wid & 3;          // 4 M groups of 64
    const int wn = wid >> 2;         // 2 N groups of 64
    const int bc = blockIdx.x;       // col tile 0..7
    const int br = blockIdx.y;       // row tile 0..63

    const __nv_bfloat16* Ah = (MODE == 0) ? g_xh : g_mh;
    const __nv_bfloat16* Al = (MODE == 0) ? g_xl : g_ml;
    const __nv_bfloat16* Bh = (MODE == 0) ? g_wh1 : g_wh2;
    const __nv_bfloat16* Bl = (MODE == 0) ? g_wl1 : g_wl2;

    // ---- loader mapping: 12 x 16B per thread per stage ----
    const int r4  = tid >> 2;       // 0..63
    const int seg = tid & 3;        // 16B segment (64B payload per row)
    const __nv_bfloat16* gA[2];
    const __nv_bfloat16* gB[2];
    gA[0] = Ah + (size_t)(br * 256 + r4) * DD + seg * 8;
    gA[1] = Al + (size_t)(br * 256 + r4) * DD + seg * 8;
    gB[0] = Bh + (size_t)(bc * 128 + r4) * DD + seg * 8;
    gB[1] = Bl + (size_t)(bc * 128 + r4) * DD + seg * 8;
    const uint32_t sload = sb + r4 * RSB + seg * 16;

    // ---- ldmatrix source offsets (within a stage) ----
    const uint32_t aoff = (uint32_t)((wm * 64 + (lane & 15)) * RSB + (lane >> 4) * 16);
    const uint32_t boff = (uint32_t)((wn * 64 + ((lane >> 4) << 3) + (lane & 7)) * RSB
                                     + ((lane >> 3) & 1) * 16);

    float acc[4][8][4];
#pragma unroll
    for (int i = 0; i < 4; i++)
#pragma unroll
        for (int j = 0; j < 8; j++)
#pragma unroll
            for (int q = 0; q < 4; q++) acc[i][j][q] = 0.f;

    // ---- prologue: fill 2 stages ----
#pragma unroll
    for (int s = 0; s < NSTG; s++) {
#pragma unroll
        for (int p = 0; p < 2; p++) {
#pragma unroll
            for (int h = 0; h < 4; h++)   // A: 256 rows
                cpasync16(sload + s * STGB + p * AOPB + h * (64 * RSB),
                          gA[p] + (size_t)h * 64 * DD + s * 32);
#pragma unroll
            for (int h = 0; h < 2; h++)   // B: 128 rows
                cpasync16(sload + s * STGB + 2 * AOPB + p * BOPB + h * (64 * RSB),
                          gB[p] + (size_t)h * 64 * DD + s * 32);
        }
        CP_COMMIT();
    }

    // ---- main loop over 32 k-chunks (R7 ordering) ----
    for (int c = 0; c < 32; c++) {
        CP_WAIT1();
        __syncthreads();
        const uint32_t stg = sb + (c & 1) * STGB;

#pragma unroll
        for (int kk = 0; kk < 2; kk++) {
            uint32_t ah[4][4], al[4][4];
#pragma unroll
            for (int mi = 0; mi < 4; mi++) {
                LDSM4(ah[mi], stg + aoff + mi * (16 * RSB) + kk * 32);
                LDSM4(al[mi], stg + AOPB + aoff + mi * (16 * RSB) + kk * 32);
            }
#pragma unroll
            for (int g = 0; g < 4; g++) {
                uint32_t bh[4], bl[4];
                LDSM4(bh, stg + 2 * AOPB + boff + g * (16 * RSB) + kk * 32);
                LDSM4(bl, stg + 2 * AOPB + BOPB + boff + g * (16 * RSB) + kk * 32);
#pragma unroll
                for (int mi = 0; mi < 4; mi++)
#pragma unroll
                    for (int nl = 0; nl < 2; nl++) {
                        const int i0 = nl * 2;
                        float* a = acc[mi][g * 2 + nl];
                        mma_bf16(a, ah[mi], bh[i0], bh[i0 + 1]);
                        mma_bf16(a, ah[mi], bl[i0], bl[i0 + 1]);
                        mma_bf16(a, al[mi], bh[i0], bh[i0 + 1]);
                    }
            }
        }
        __syncthreads();
        if (c + NSTG < 32) {
            const uint32_t dst = sload + (c & 1) * STGB;
#pragma unroll
            for (int p = 0; p < 2; p++) {
#pragma unroll
                for (int h = 0; h < 4; h++)
                    cpasync16(dst + p * AOPB + h * (64 * RSB),
                              gA[p] + (size_t)h * 64 * DD + (c + NSTG) * 32);
#pragma unroll
                for (int h = 0; h < 2; h++)
                    cpasync16(dst + 2 * AOPB + p * BOPB + h * (64 * RSB),
                              gB[p] + (size_t)h * 64 * DD + (c + NSTG) * 32);
            }
        }
        CP_COMMIT();
    }

    // ---- epilogue: fused scale / bias+residual, direct stores ----
    const int mbase = br * 256 + wm * 64;
    const int nbase = bc * 128 + wn * 64;
    const int rq = lane >> 2;
    const int cq = (lane & 3) * 2;
    float csum[8][2];
#pragma unroll
    for (int ni = 0; ni < 8; ni++) { csum[ni][0] = 0.f; csum[ni][1] = 0.f; }

#pragma unroll
    for (int ni = 0; ni < 8; ni++) {
        const int col = nbase + ni * 8 + cq;
        float f0, f1;
        if (MODE == 0) {
            f0 = cosf(aux[col] * PI_F);
            f1 = cosf(aux[col + 1] * PI_F);
        } else {
            f0 = aux[col];
            f1 = aux[col + 1];
        }
#pragma unroll
        for (int mi = 0; mi < 4; mi++) {
            const int r0 = mbase + mi * 16 + rq;
            float* p0 = g_heads + (size_t)r0 * DD + col;
            float* p1 = g_heads + (size_t)(r0 + 8) * DD + col;
            float2 o0, o1;
            if (MODE == 0) {
                o0.x = acc[mi][ni][0] * f0; o0.y = acc[mi][ni][1] * f1;
                o1.x = acc[mi][ni][2] * f0; o1.y = acc[mi][ni][3] * f1;
                csum[ni][0] += o0.x + o1.x;
                csum[ni][1] += o0.y + o1.y;
            } else {
                float2 x0 = *(const float2*)(xres + (size_t)r0 * DD + col);
                float2 x1 = *(const float2*)(xres + (size_t)(r0 + 8) * DD + col);
                o0.x = acc[mi][ni][0] + f0 + x0.x; o0.y = acc[mi][ni][1] + f1 + x0.y;
                o1.x = acc[mi][ni][2] + f0 + x1.x; o1.y = acc[mi][ni][3] + f1 + x1.y;
            }
            *(float2*)p0 = o0;
            *(float2*)p1 = o1;
        }
    }

    if (MODE == 0) {
        // deterministic colsum: shfl over rq lanes, stage per-wm values in
        // smem, fixed-order sum by 128 threads, write per-row-tile partial.
        float* scs = (float*)sm;   // stages dead (mainloop ended with sync)
        __syncthreads();
#pragma unroll
        for (int ni = 0; ni < 8; ni++) {
            float v0 = csum[ni][0], v1 = csum[ni][1];
#pragma unroll
            for (int o = 4; o < 32; o <<= 1) {
                v0 += __shfl_xor_sync(0xffffffffu, v0, o);
                v1 += __shfl_xor_sync(0xffffffffu, v1, o);
            }
            if (rq == 0) {
                scs[wm * 128 + wn * 64 + ni * 8 + cq] = v0;
                scs[wm * 128 + wn * 64 + ni * 8 + cq + 1] = v1;
            }
        }
        __syncthreads();
        if (tid < 128) {
            float s = scs[tid];
            s += scs[128 + tid];
            s += scs[256 + tid];
            s += scs[384 + tid];
            g_part[(size_t)br * DD + bc * 128 + tid] = s;
        }
    }
}

// ---------------------------------------------------------------------------
// Fused summary-reduce + polarity + impedance.  grid=BB, 1024 threads.
// ---------------------------------------------------------------------------
__global__ void polarity_fused(const float* __restrict__ pol_W,
                               const float* __restrict__ pol_b,
                               const float* __restrict__ W1,
                               const float* __restrict__ b1,
                               const float* __restrict__ W2,
                               const float* __restrict__ b2,
                               float* __restrict__ imp_out)
{
    const int b = blockIdx.x;
    const int tid = threadIdx.x;
    __shared__ float s_sum[DD];
    __shared__ float s_pol[HH * PP];

    // summary for batch b: fixed-order sum of its 16 row-tile partials
    float s = 0.f;
#pragma unroll
    for (int c = 0; c < 16; c++)
        s += g_part[(size_t)(b * 16 + c) * DD + tid];
    s_sum[tid] = s * (1.0f / (float)SS);
    __syncthreads();

    // dot: tid = h*128 + p*4 + q ; 4 lanes per (h,p), 32 k each
    const int h = tid >> 7;
    const int p = (tid >> 2) & 31;
    const int q = tid & 3;
    const float4* pw = (const float4*)(pol_W + (size_t)(h * PP + p) * KK + q * 32);
    const float* xs = s_sum + h * KK + q * 32;
    float acc = 0.f;
#pragma unroll
    for (int k4 = 0; k4 < 8; k4++) {
        float4 w = pw[k4];
        acc += xs[k4 * 4 + 0] * w.x + xs[k4 * 4 + 1] * w.y
             + xs[k4 * 4 + 2] * w.z + xs[k4 * 4 + 3] * w.w;
    }
    acc += __shfl_xor_sync(0xffffffffu, acc, 1);
    acc += __shfl_xor_sync(0xffffffffu, acc, 2);
    if (q == 0) s_pol[h * PP + p] = tanhf(acc + pol_b[h * PP + p]);
    __syncthreads();

    // normalize: warp w = head w
    const int wid = tid >> 5, lane = tid & 31;
    if (wid < HH) {
        float pv = s_pol[wid * PP + lane];
        float ss2 = pv * pv;
#pragma unroll
        for (int o = 16; o; o >>= 1) ss2 += __shfl_xor_sync(0xffffffffu, ss2, o);
        s_pol[wid * PP + lane] = pv / fmaxf(sqrtf(ss2), 1e-12f);
    }
    __syncthreads();

    // impedance: 64 (i,j) pairs
    if (tid < HH * HH) {
        const int i = tid >> 3;
        const int j = tid & 7;
        float d = 0.f;
#pragma unroll
        for (int pp = 0; pp < PP; pp++) d += s_pol[i * PP + pp] * s_pol[j * PP + pp];

        float sum2 = b2[0];
#pragma unroll
        for (int c = 0; c < 16; c++) {
            float z = d * W1[c] + b1[c];
            float g = 0.5f * z * (1.f + erff(z * 0.70710678118654752f));
            sum2 += g * W2[c];
        }
        float imp = (sum2 > 0.f) ? sum2 + log1pf(expf(-sum2)) : log1pf(expf(sum2));
        if (i == j) imp = 0.f;
        imp_out[b * 64 + tid] = imp;
        g_coef[b * 64 + tid] = (i == j) ? 0.f : 0.1f / (1.f + imp);
    }
}

// ---------------------------------------------------------------------------
// Cross-head mixing with causal scale -> bf16 hi/lo (GEMM2 A operand)
// ---------------------------------------------------------------------------
__global__ void mixing_kernel(const int* __restrict__ causal)
{
    const int bs = blockIdx.x;          // 0..16383
    const int b = bs >> 12;
    const int s = bs & (SS - 1);
    const int k = threadIdx.x;          // 0..127
    __shared__ float sc[HH * HH];
    if (threadIdx.x < HH * HH) sc[threadIdx.x] = g_coef[b * 64 + threadIdx.x];
    __syncthreads();

    const float* row = g_heads + (size_t)bs * DD;
    float v[HH];
#pragma unroll
    for (int j = 0; j < HH; j++) v[j] = row[j * KK + k];

    const float scale = (*causal) ? (float)(s + 1) * (1.0f / (float)SS) : 1.0f;

    __nv_bfloat16* oh = g_mh + (size_t)bs * DD;
    __nv_bfloat16* ol = g_ml + (size_t)bs * DD;
#pragma unroll
    for (int i = 0; i < HH; i++) {
        float t = 0.f;
#pragma unroll
        for (int j = 0; j < HH; j++) t += sc[i * 8 + j] * v[j];
        float val = v[i] + scale * t;
        __nv_bfloat16 h = __float2bfloat16(val);
        oh[i * KK + k] = h;
        ol[i * KK + k] = __float2bfloat16(val - __bfloat162float(h));
    }
}

// ---------------------------------------------------------------------------
// LayerNorm over D (y lives in g_heads after GEMM2)
// ---------------------------------------------------------------------------
__global__ void layernorm_kernel(const float* __restrict__ gamma,
                                 const float* __restrict__ beta,
                                 float* __restrict__ out)
{
    const int row = blockIdx.x;
    const int t = threadIdx.x;          // 0..255
    const float4 v = ((const float4*)(g_heads + (size_t)row * DD))[t];
    float s  = v.x + v.y + v.z + v.w;
    float s2 = v.x * v.x + v.y * v.y + v.z * v.z + v.w * v.w;

#pragma unroll
    for (int o = 16; o; o >>= 1) {
        s  += __shfl_xor_sync(0xffffffffu, s, o);
        s2 += __shfl_xor_sync(0xffffffffu, s2, o);
    }
    __shared__ float sh[8], sh2[8];
    const int w = t >> 5, lane = t & 31;
    if (lane == 0) { sh[w] = s; sh2[w] = s2; }
    __syncthreads();
    if (w == 0) {
        s  = (lane < 8) ? sh[lane]  : 0.f;
        s2 = (lane < 8) ? sh2[lane] : 0.f;
#pragma unroll
        for (int o = 4; o; o >>= 1) {
            s  += __shfl_xor_sync(0xffffffffu, s, o);
            s2 += __shfl_xor_sync(0xffffffffu, s2, o);
        }
        if (lane == 0) { sh[0] = s; sh2[0] = s2; }
    }
    __syncthreads();
    const float mu  = sh[0] * (1.f / (float)DD);
    const float var = sh2[0] * (1.f / (float)DD) - mu * mu;
    const float inv = rsqrtf(var + 1e-5f);

    const float4 g4 = ((const float4*)gamma)[t];
    const float4 b4 = ((const float4*)beta)[t];
    float4 o4;
    o4.x = (v.x - mu) * inv * g4.x + b4.x;
    o4.y = (v.y - mu) * inv * g4.y + b4.y;
    o4.z = (v.z - mu) * inv * g4.z + b4.z;
    o4.w = (v.w - mu) * inv * g4.w + b4.w;
    ((float4*)(out + (size_t)row * DD))[t] = o4;
}

// ---------------------------------------------------------------------------
extern "C" void kernel_launch(void* const* d_in, const int* in_sizes, int n_in,
                              void* d_out, int out_size)
{
    const float* x      = (const float*)d_in[0];   // (B,S,D)
    const float* W_proj = (const float*)d_in[1];   // (H,K,D) -> (1024,1024)
    const float* freqs  = (const float*)d_in[2];   // (H,K) -> 1024
    const float* pol_W  = (const float*)d_in[3];
    const float* pol_b  = (const float*)d_in[4];
    const float* imp_W1 = (const float*)d_in[5];
    const float* imp_b1 = (const float*)d_in[6];
    const float* imp_W2 = (const float*)d_in[7];
    const float* imp_b2 = (const float*)d_in[8];
    const float* out_W  = (const float*)d_in[9];
    const float* out_b  = (const float*)d_in[10];
    const float* ln_g   = (const float*)d_in[11];
    const float* ln_b   = (const float*)d_in[12];
    const int*   causal = (const int*)d_in[13];

    float* out = (float*)d_out;
    float* imp_out = out + (out_size - BB * HH * HH);  // impedance tail

    cudaFuncSetAttribute(gemm_mma<0>, cudaFuncAttributeMaxDynamicSharedMemorySize, GEMM_SMEM);
    cudaFuncSetAttribute(gemm_mma<1>, cudaFuncAttributeMaxDynamicSharedMemorySize, GEMM_SMEM);

    dim3 ggrid(DD / 128, NROW / 256);  // (8, 64)

    // 0) bf16 hi/lo splits of x, W_proj, out_W (single launch)
    convert_split_all<<<NBX + 2 * NBW, 256>>>(x, W_proj, out_W);
    // 1) heads = (x @ W_proj^T) * cos(freq*pi) -> g_heads, colsums -> g_part
    gemm_mma<0><<<ggrid, 256, GEMM_SMEM>>>(x, freqs);
    // 2) summary reduce + pol / impedance / coef (fused, one launch)
    polarity_fused<<<BB, 1024>>>(pol_W, pol_b, imp_W1, imp_b1, imp_W2, imp_b2, imp_out);
    // 3) cross-head mixing with causal scale     -> g_mh/g_ml (bf16 split)
    mixing_kernel<<<NROW, 128>>>(causal);
    // 4) y = mixed @ out_W^T + out_b + x         -> g_heads   [mma.sync 3xbf16]
    gemm_mma<1><<<ggrid, 256, GEMM_SMEM>>>(x, out_b);
    // 5) LayerNorm -> d_out
    layernorm_kernel<<<NROW, 256>>>(ln_g, ln_b, out);
}

// round 13
// speedup vs baseline: 1.1334x; 1.1334x over previous
#include <cuda_runtime.h>
#include <cuda_bf16.h>
#include <math.h>
#include <stdint.h>

// Problem constants
#define BB 4
#define SS 4096
#define DD 1024
#define HH 8
#define KK 128
#define PP 32
#define NROW (BB*SS)          // 16384
#define PI_F 3.14159265358979f

// ---------------------------------------------------------------------------
// Device-global scratch (no allocations allowed)
// ---------------------------------------------------------------------------
__device__ __nv_bfloat16 g_xh[(size_t)NROW * DD];   // bf16 hi of x
__device__ __nv_bfloat16 g_xl[(size_t)NROW * DD];   // bf16 lo of x
__device__ __nv_bfloat16 g_mh[(size_t)NROW * DD];   // bf16 hi of mixed
__device__ __nv_bfloat16 g_ml[(size_t)NROW * DD];   // bf16 lo of mixed
__device__ __nv_bfloat16 g_wh1[DD * DD], g_wl1[DD * DD];  // W_proj hi/lo
__device__ __nv_bfloat16 g_wh2[DD * DD], g_wl2[DD * DD];  // out_W hi/lo
__device__ float g_heads[(size_t)NROW * DD];        // heads fp32, later y
__device__ float g_part[128 * DD];                  // per-row-tile column sums
__device__ float g_coef[BB * HH * HH];              // 0.1/(1+imp), zero diag

__device__ __forceinline__ uint32_t smem_to_u32(const void* smem_ptr) {
    uint32_t addr;
    asm("{ .reg .u64 tmp; cvta.to.shared.u64 tmp, %1; cvt.u32.u64 %0, tmp; }"
        : "=r"(addr) : "l"(smem_ptr));
    return addr;
}

__device__ __forceinline__ void cpasync16(uint32_t dst, const void* src) {
    asm volatile("cp.async.cg.shared.global [%0], [%1], 16;"
                 :: "r"(dst), "l"(src) : "memory");
}

#define CP_COMMIT() asm volatile("cp.async.commit_group;" ::: "memory")
#define CP_WAIT1()  asm volatile("cp.async.wait_group 1;" ::: "memory")

#define LDSM4(r, addr) \
    asm volatile("ldmatrix.sync.aligned.m8n8.x4.shared.b16 {%0,%1,%2,%3}, [%4];" \
        : "=r"((r)[0]), "=r"((r)[1]), "=r"((r)[2]), "=r"((r)[3]) : "r"(addr))

__device__ __forceinline__ void mma_bf16(float* c, const uint32_t* a,
                                         uint32_t b0, uint32_t b1) {
    asm volatile(
        "mma.sync.aligned.m16n8k16.row.col.f32.bf16.bf16.f32 "
        "{%0,%1,%2,%3}, {%4,%5,%6,%7}, {%8,%9}, {%0,%1,%2,%3};"
        : "+f"(c[0]), "+f"(c[1]), "+f"(c[2]), "+f"(c[3])
        : "r"(a[0]), "r"(a[1]), "r"(a[2]), "r"(a[3]), "r"(b0), "r"(b1));
}

// ---------------------------------------------------------------------------
// bf16 hi/lo split conversion: all three tensors in ONE launch.
// ---------------------------------------------------------------------------
#define NBX (NROW * DD / 4 / 256)   // 4096 blocks for x
#define NBW (DD * DD / 4 / 256)     // 1024 blocks per weight
__global__ void convert_split_all(const float* __restrict__ x,
                                  const float* __restrict__ w1,
                                  const float* __restrict__ w2)
{
    int blk = blockIdx.x;
    const float* src;
    __nv_bfloat16 *hp, *lp;
    int i;
    if (blk < NBX) {
        src = x;  hp = g_xh;  lp = g_xl;
        i = blk * 256 + threadIdx.x;
    } else if (blk < NBX + NBW) {
        src = w1; hp = g_wh1; lp = g_wl1;
        i = (blk - NBX) * 256 + threadIdx.x;
    } else {
        src = w2; hp = g_wh2; lp = g_wl2;
        i = (blk - NBX - NBW) * 256 + threadIdx.x;
    }
    float4 v = ((const float4*)src)[i];
    __nv_bfloat162 h01 = __floats2bfloat162_rn(v.x, v.y);
    __nv_bfloat162 h23 = __floats2bfloat162_rn(v.z, v.w);
    __nv_bfloat162 l01 = __floats2bfloat162_rn(v.x - __low2float(h01),
                                               v.y - __high2float(h01));
    __nv_bfloat162 l23 = __floats2bfloat162_rn(v.z - __low2float(h23),
                                               v.w - __high2float(h23));
    ((__nv_bfloat162*)hp)[2 * i + 0] = h01;
    ((__nv_bfloat162*)hp)[2 * i + 1] = h23;
    ((__nv_bfloat162*)lp)[2 * i + 0] = l01;
    ((__nv_bfloat162*)lp)[2 * i + 1] = l23;
}

// ---------------------------------------------------------------------------
// mma.sync GEMM: C[n,m] = sum_d A[n,d]*W[m,d] via 3xbf16 split.
// 128x128 tile, BK=32, 128 threads (4 warps, warp tile 64x64), 2-stage
// cp.async pipeline, 2 CTAs/SM.  (R7/R10 config — proven best.)
//   MODE 0: A = x(hi/lo),   epi: * cos(freq[m]*pi) -> g_heads, + colsum->g_part
//   MODE 1: A = mixed(hi/lo), epi: + out_b[m] + x[n,m]        -> g_heads
// SMEM rows padded to 80B -> conflict-free ldmatrix phases.
// ---------------------------------------------------------------------------
#define RSB   80                 // row stride bytes (32 bf16 + 16B pad)
#define OPB   (128 * RSB)        // 10240 bytes per operand tile
#define STGB  (4 * OPB)          // 40960 bytes per stage (Ah|Al|Bh|Bl)
#define NSTG  2
#define GEMM_SMEM (NSTG * STGB)  // 81920

template<int MODE>
__global__ __launch_bounds__(128, 2)
void gemm_mma(const float* __restrict__ xres, const float* __restrict__ aux)
{
    extern __shared__ char sm[];
    const uint32_t sb = smem_to_u32(sm);
    const int tid = threadIdx.x;
    const int lane = tid & 31;
    const int wid = tid >> 5;        // 0..3
    const int wm = wid & 1;          // 2 M groups of 64
    const int wn = wid >> 1;         // 2 N groups of 64
    const int bc = blockIdx.x;       // col tile 0..7
    const int br = blockIdx.y;       // row tile 0..127

    const __nv_bfloat16* Ah = (MODE == 0) ? g_xh : g_mh;
    const __nv_bfloat16* Al = (MODE == 0) ? g_xl : g_ml;
    const __nv_bfloat16* Bh = (MODE == 0) ? g_wh1 : g_wh2;
    const __nv_bfloat16* Bl = (MODE == 0) ? g_wl1 : g_wl2;

    // ---- loader mapping: 16 x 16B per thread per stage ----
    const int r4  = tid >> 2;       // 0..31
    const int seg = tid & 3;        // 16B segment (64B of payload per row)
    const __nv_bfloat16* gbase[4];
    gbase[0] = Ah + (size_t)(br * 128 + r4) * DD + seg * 8;
    gbase[1] = Al + (size_t)(br * 128 + r4) * DD + seg * 8;
    gbase[2] = Bh + (size_t)(bc * 128 + r4) * DD + seg * 8;
    gbase[3] = Bl + (size_t)(bc * 128 + r4) * DD + seg * 8;
    const uint32_t sload = sb + r4 * RSB + seg * 16;

    // ---- ldmatrix source offsets (within a stage) ----
    const uint32_t aoff = (uint32_t)((wm * 64 + (lane & 15)) * RSB + (lane >> 4) * 16);
    const uint32_t boff = (uint32_t)((wn * 64 + ((lane >> 4) << 3) + (lane & 7)) * RSB
                                     + ((lane >> 3) & 1) * 16);

    float acc[4][8][4];
#pragma unroll
    for (int i = 0; i < 4; i++)
#pragma unroll
        for (int j = 0; j < 8; j++)
#pragma unroll
            for (int q = 0; q < 4; q++) acc[i][j][q] = 0.f;

    // ---- prologue: fill 2 stages ----
#pragma unroll
    for (int s = 0; s < NSTG; s++) {
#pragma unroll
        for (int op = 0; op < 4; op++)
#pragma unroll
            for (int h = 0; h < 4; h++)
                cpasync16(sload + s * STGB + op * OPB + h * (32 * RSB),
                          gbase[op] + (size_t)h * 32 * DD + s * 32);
        CP_COMMIT();
    }

    // ---- main loop over 32 k-chunks (R7 ordering) ----
    for (int c = 0; c < 32; c++) {
        CP_WAIT1();
        __syncthreads();
        const uint32_t stg = sb + (c & 1) * STGB;

#pragma unroll
        for (int kk = 0; kk < 2; kk++) {
            uint32_t ah[4][4], al[4][4];
#pragma unroll
            for (int mi = 0; mi < 4; mi++) {
                LDSM4(ah[mi], stg + aoff + mi * (16 * RSB) + kk * 32);
                LDSM4(al[mi], stg + OPB + aoff + mi * (16 * RSB) + kk * 32);
            }
#pragma unroll
            for (int g = 0; g < 4; g++) {
                uint32_t bh[4], bl[4];
                LDSM4(bh, stg + 2 * OPB + boff + g * (16 * RSB) + kk * 32);
                LDSM4(bl, stg + 3 * OPB + boff + g * (16 * RSB) + kk * 32);
#pragma unroll
                for (int mi = 0; mi < 4; mi++)
#pragma unroll
                    for (int nl = 0; nl < 2; nl++) {
                        const int i0 = nl * 2;
                        float* a = acc[mi][g * 2 + nl];
                        mma_bf16(a, ah[mi], bh[i0], bh[i0 + 1]);
                        mma_bf16(a, ah[mi], bl[i0], bl[i0 + 1]);
                        mma_bf16(a, al[mi], bh[i0], bh[i0 + 1]);
                    }
            }
        }
        __syncthreads();
        if (c + NSTG < 32) {
            const uint32_t dst = sload + (c & 1) * STGB;
#pragma unroll
            for (int op = 0; op < 4; op++)
#pragma unroll
                for (int h = 0; h < 4; h++)
                    cpasync16(dst + op * OPB + h * (32 * RSB),
                              gbase[op] + (size_t)h * 32 * DD + (c + NSTG) * 32);
        }
        CP_COMMIT();
    }

    // ---- epilogue: fused scale / bias+residual, direct stores ----
    const int mbase = br * 128 + wm * 64;
    const int nbase = bc * 128 + wn * 64;
    const int rq = lane >> 2;
    const int cq = (lane & 3) * 2;
    float csum[8][2];   // MODE 0 only: per-thread column partial sums
#pragma unroll
    for (int ni = 0; ni < 8; ni++) { csum[ni][0] = 0.f; csum[ni][1] = 0.f; }

#pragma unroll
    for (int ni = 0; ni < 8; ni++) {
        const int col = nbase + ni * 8 + cq;
        float f0, f1;
        if (MODE == 0) {
            f0 = cosf(aux[col] * PI_F);
            f1 = cosf(aux[col + 1] * PI_F);
        } else {
            f0 = aux[col];
            f1 = aux[col + 1];
        }
#pragma unroll
        for (int mi = 0; mi < 4; mi++) {
            const int r0 = mbase + mi * 16 + rq;
            float* p0 = g_heads + (size_t)r0 * DD + col;
            float* p1 = g_heads + (size_t)(r0 + 8) * DD + col;
            float2 o0, o1;
            if (MODE == 0) {
                o0.x = acc[mi][ni][0] * f0; o0.y = acc[mi][ni][1] * f1;
                o1.x = acc[mi][ni][2] * f0; o1.y = acc[mi][ni][3] * f1;
                csum[ni][0] += o0.x + o1.x;
                csum[ni][1] += o0.y + o1.y;
            } else {
                float2 x0 = *(const float2*)(xres + (size_t)r0 * DD + col);
                float2 x1 = *(const float2*)(xres + (size_t)(r0 + 8) * DD + col);
                o0.x = acc[mi][ni][0] + f0 + x0.x; o0.y = acc[mi][ni][1] + f1 + x0.y;
                o1.x = acc[mi][ni][2] + f0 + x1.x; o1.y = acc[mi][ni][3] + f1 + x1.y;
            }
            *(float2*)p0 = o0;
            *(float2*)p1 = o1;
        }
    }

    if (MODE == 0) {
        // deterministic colsum: shfl over rq lanes; smem accumulate with
        // exactly 2 commutative adds per slot; write per-row-tile partial.
        float* scs = (float*)sm;   // stages dead (mainloop ended with sync)
        scs[tid] = 0.f;
        __syncthreads();
#pragma unroll
        for (int ni = 0; ni < 8; ni++) {
            float v0 = csum[ni][0], v1 = csum[ni][1];
#pragma unroll
            for (int o = 4; o < 32; o <<= 1) {
                v0 += __shfl_xor_sync(0xffffffffu, v0, o);
                v1 += __shfl_xor_sync(0xffffffffu, v1, o);
            }
            if (rq == 0) {
                atomicAdd(&scs[wn * 64 + ni * 8 + cq], v0);
                atomicAdd(&scs[wn * 64 + ni * 8 + cq + 1], v1);
            }
        }
        __syncthreads();
        g_part[(size_t)br * DD + bc * 128 + tid] = scs[tid];
    }
}

// ---------------------------------------------------------------------------
// Fused summary-reduce + polarity + impedance.  grid=BB, 1024 threads.
// Batch b owns row tiles [b*32, b*32+32) of g_part.
// ---------------------------------------------------------------------------
__global__ void polarity_fused(const float* __restrict__ pol_W,
                               const float* __restrict__ pol_b,
                               const float* __restrict__ W1,
                               const float* __restrict__ b1,
                               const float* __restrict__ W2,
                               const float* __restrict__ b2,
                               float* __restrict__ imp_out)
{
    const int b = blockIdx.x;
    const int tid = threadIdx.x;
    __shared__ float s_sum[DD];
    __shared__ float s_pol[HH * PP];

    // summary for batch b: fixed-order sum of its 32 row-tile partials
    float s = 0.f;
#pragma unroll 8
    for (int c = 0; c < 32; c++)
        s += g_part[(size_t)(b * 32 + c) * DD + tid];
    s_sum[tid] = s * (1.0f / (float)SS);
    __syncthreads();

    // dot: tid = h*128 + p*4 + q ; 4 lanes per (h,p), 32 k each
    const int h = tid >> 7;
    const int p = (tid >> 2) & 31;
    const int q = tid & 3;
    const float4* pw = (const float4*)(pol_W + (size_t)(h * PP + p) * KK + q * 32);
    const float* xs = s_sum + h * KK + q * 32;
    float acc = 0.f;
#pragma unroll
    for (int k4 = 0; k4 < 8; k4++) {
        float4 w = pw[k4];
        acc += xs[k4 * 4 + 0] * w.x + xs[k4 * 4 + 1] * w.y
             + xs[k4 * 4 + 2] * w.z + xs[k4 * 4 + 3] * w.w;
    }
    acc += __shfl_xor_sync(0xffffffffu, acc, 1);
    acc += __shfl_xor_sync(0xffffffffu, acc, 2);
    if (q == 0) s_pol[h * PP + p] = tanhf(acc + pol_b[h * PP + p]);
    __syncthreads();

    // normalize: warp w = head w
    const int wid = tid >> 5, lane = tid & 31;
    if (wid < HH) {
        float pv = s_pol[wid * PP + lane];
        float ss2 = pv * pv;
#pragma unroll
        for (int o = 16; o; o >>= 1) ss2 += __shfl_xor_sync(0xffffffffu, ss2, o);
        s_pol[wid * PP + lane] = pv / fmaxf(sqrtf(ss2), 1e-12f);
    }
    __syncthreads();

    // impedance: 64 (i,j) pairs
    if (tid < HH * HH) {
        const int i = tid >> 3;
        const int j = tid & 7;
        float d = 0.f;
#pragma unroll
        for (int pp = 0; pp < PP; pp++) d += s_pol[i * PP + pp] * s_pol[j * PP + pp];

        float sum2 = b2[0];
#pragma unroll
        for (int c = 0; c < 16; c++) {
            float z = d * W1[c] + b1[c];
            float g = 0.5f * z * (1.f + erff(z * 0.70710678118654752f));
            sum2 += g * W2[c];
        }
        float imp = (sum2 > 0.f) ? sum2 + log1pf(expf(-sum2)) : log1pf(expf(sum2));
        if (i == j) imp = 0.f;
        imp_out[b * 64 + tid] = imp;
        g_coef[b * 64 + tid] = (i == j) ? 0.f : 0.1f / (1.f + imp);
    }
}

// ---------------------------------------------------------------------------
// Cross-head mixing with causal scale -> bf16 hi/lo (GEMM2 A operand)
// ---------------------------------------------------------------------------
__global__ void mixing_kernel(const int* __restrict__ causal)
{
    const int bs = blockIdx.x;          // 0..16383
    const int b = bs >> 12;
    const int s = bs & (SS - 1);
    const int k = threadIdx.x;          // 0..127
    __shared__ float sc[HH * HH];
    if (threadIdx.x < HH * HH) sc[threadIdx.x] = g_coef[b * 64 + threadIdx.x];
    __syncthreads();

    const float* row = g_heads + (size_t)bs * DD;
    float v[HH];
#pragma unroll
    for (int j = 0; j < HH; j++) v[j] = row[j * KK + k];

    const float scale = (*causal) ? (float)(s + 1) * (1.0f / (float)SS) : 1.0f;

    __nv_bfloat16* oh = g_mh + (size_t)bs * DD;
    __nv_bfloat16* ol = g_ml + (size_t)bs * DD;
#pragma unroll
    for (int i = 0; i < HH; i++) {
        float t = 0.f;
#pragma unroll
        for (int j = 0; j < HH; j++) t += sc[i * 8 + j] * v[j];
        float val = v[i] + scale * t;
        __nv_bfloat16 h = __float2bfloat16(val);
        oh[i * KK + k] = h;
        ol[i * KK + k] = __float2bfloat16(val - __bfloat162float(h));
    }
}

// ---------------------------------------------------------------------------
// LayerNorm over D (y lives in g_heads after GEMM2)
// ---------------------------------------------------------------------------
__global__ void layernorm_kernel(const float* __restrict__ gamma,
                                 const float* __restrict__ beta,
                                 float* __restrict__ out)
{
    const int row = blockIdx.x;
    const int t = threadIdx.x;          // 0..255
    const float4 v = ((const float4*)(g_heads + (size_t)row * DD))[t];
    float s  = v.x + v.y + v.z + v.w;
    float s2 = v.x * v.x + v.y * v.y + v.z * v.z + v.w * v.w;

#pragma unroll
    for (int o = 16; o; o >>= 1) {
        s  += __shfl_xor_sync(0xffffffffu, s, o);
        s2 += __shfl_xor_sync(0xffffffffu, s2, o);
    }
    __shared__ float sh[8], sh2[8];
    const int w = t >> 5, lane = t & 31;
    if (lane == 0) { sh[w] = s; sh2[w] = s2; }
    __syncthreads();
    if (w == 0) {
        s  = (lane < 8) ? sh[lane]  : 0.f;
        s2 = (lane < 8) ? sh2[lane] : 0.f;
#pragma unroll
        for (int o = 4; o; o >>= 1) {
            s  += __shfl_xor_sync(0xffffffffu, s, o);
            s2 += __shfl_xor_sync(0xffffffffu, s2, o);
        }
        if (lane == 0) { sh[0] = s; sh2[0] = s2; }
    }
    __syncthreads();
    const float mu  = sh[0] * (1.f / (float)DD);
    const float var = sh2[0] * (1.f / (float)DD) - mu * mu;
    const float inv = rsqrtf(var + 1e-5f);

    const float4 g4 = ((const float4*)gamma)[t];
    const float4 b4 = ((const float4*)beta)[t];
    float4 o4;
    o4.x = (v.x - mu) * inv * g4.x + b4.x;
    o4.y = (v.y - mu) * inv * g4.y + b4.y;
    o4.z = (v.z - mu) * inv * g4.z + b4.z;
    o4.w = (v.w - mu) * inv * g4.w + b4.w;
    ((float4*)(out + (size_t)row * DD))[t] = o4;
}

// ---------------------------------------------------------------------------
extern "C" void kernel_launch(void* const* d_in, const int* in_sizes, int n_in,
                              void* d_out, int out_size)
{
    const float* x      = (const float*)d_in[0];   // (B,S,D)
    const float* W_proj = (const float*)d_in[1];   // (H,K,D) -> (1024,1024)
    const float* freqs  = (const float*)d_in[2];   // (H,K) -> 1024
    const float* pol_W  = (const float*)d_in[3];
    const float* pol_b  = (const float*)d_in[4];
    const float* imp_W1 = (const float*)d_in[5];
    const float* imp_b1 = (const float*)d_in[6];
    const float* imp_W2 = (const float*)d_in[7];
    const float* imp_b2 = (const float*)d_in[8];
    const float* out_W  = (const float*)d_in[9];
    const float* out_b  = (const float*)d_in[10];
    const float* ln_g   = (const float*)d_in[11];
    const float* ln_b   = (const float*)d_in[12];
    const int*   causal = (const int*)d_in[13];

    float* out = (float*)d_out;
    float* imp_out = out + (out_size - BB * HH * HH);  // impedance tail

    cudaFuncSetAttribute(gemm_mma<0>, cudaFuncAttributeMaxDynamicSharedMemorySize, GEMM_SMEM);
    cudaFuncSetAttribute(gemm_mma<1>, cudaFuncAttributeMaxDynamicSharedMemorySize, GEMM_SMEM);

    dim3 ggrid(DD / 128, NROW / 128);  // (8, 128)

    // 0) bf16 hi/lo splits of x, W_proj, out_W (single launch)
    convert_split_all<<<NBX + 2 * NBW, 256>>>(x, W_proj, out_W);
    // 1) heads = (x @ W_proj^T) * cos(freq*pi) -> g_heads, colsums -> g_part
    gemm_mma<0><<<ggrid, 128, GEMM_SMEM>>>(x, freqs);
    // 2) summary reduce + pol / impedance / coef (fused, one launch)
    polarity_fused<<<BB, 1024>>>(pol_W, pol_b, imp_W1, imp_b1, imp_W2, imp_b2, imp_out);
    // 3) cross-head mixing with causal scale     -> g_mh/g_ml (bf16 split)
    mixing_kernel<<<NROW, 128>>>(causal);
    // 4) y = mixed @ out_W^T + out_b + x         -> g_heads   [mma.sync 3xbf16]
    gemm_mma<1><<<ggrid, 128, GEMM_SMEM>>>(x, out_b);
    // 5) LayerNorm -> d_out
    layernorm_kernel<<<NROW, 256>>>(ln_g, ln_b, out);
}

// round 15
// speedup vs baseline: 1.5191x; 1.3403x over previous
#include <cuda_runtime.h>
#include <cuda_fp16.h>
#include <math.h>
#include <stdint.h>

// Problem constants
#define BB 4
#define SS 4096
#define DD 1024
#define HH 8
#define KK 128
#define PP 32
#define NROW (BB*SS)          // 16384
#define PI_F 3.14159265358979f

// ---------------------------------------------------------------------------
// Device-global scratch (no allocations allowed)
// ---------------------------------------------------------------------------
__device__ __half g_xh[(size_t)NROW * DD];   // fp16 hi of x
__device__ __half g_xl[(size_t)NROW * DD];   // fp16 lo of x (exact residual)
__device__ __half g_mh[(size_t)NROW * DD];   // fp16 hi of mixed
__device__ __half g_ml[(size_t)NROW * DD];   // fp16 lo of mixed
__device__ __half g_wh1[DD * DD];            // W_proj fp16 (single)
__device__ __half g_wh2[DD * DD];            // out_W fp16 (single)
__device__ float g_heads[(size_t)NROW * DD]; // heads fp32, later y
__device__ float g_part[128 * DD];           // per-row-tile column sums
__device__ float g_coef[BB * HH * HH];       // 0.1/(1+imp), zero diag

__device__ __forceinline__ uint32_t smem_to_u32(const void* smem_ptr) {
    uint32_t addr;
    asm("{ .reg .u64 tmp; cvta.to.shared.u64 tmp, %1; cvt.u32.u64 %0, tmp; }"
        : "=r"(addr) : "l"(smem_ptr));
    return addr;
}

__device__ __forceinline__ void cpasync16(uint32_t dst, const void* src) {
    asm volatile("cp.async.cg.shared.global [%0], [%1], 16;"
                 :: "r"(dst), "l"(src) : "memory");
}

#define CP_COMMIT() asm volatile("cp.async.commit_group;" ::: "memory")
#define CP_WAIT1()  asm volatile("cp.async.wait_group 1;" ::: "memory")

#define LDSM4(r, addr) \
    asm volatile("ldmatrix.sync.aligned.m8n8.x4.shared.b16 {%0,%1,%2,%3}, [%4];" \
        : "=r"((r)[0]), "=r"((r)[1]), "=r"((r)[2]), "=r"((r)[3]) : "r"(addr))

__device__ __forceinline__ void mma_fp16(float* c, const uint32_t* a,
                                         uint32_t b0, uint32_t b1) {
    asm volatile(
        "mma.sync.aligned.m16n8k16.row.col.f32.f16.f16.f32 "
        "{%0,%1,%2,%3}, {%4,%5,%6,%7}, {%8,%9}, {%0,%1,%2,%3};"
        : "+f"(c[0]), "+f"(c[1]), "+f"(c[2]), "+f"(c[3])
        : "r"(a[0]), "r"(a[1]), "r"(a[2]), "r"(a[3]), "r"(b0), "r"(b1));
}

// ---------------------------------------------------------------------------
// fp16 conversion: x -> hi/lo split; W_proj, out_W -> single fp16.  ONE launch.
// ---------------------------------------------------------------------------
#define NBX (NROW * DD / 4 / 256)   // 4096 blocks for x
#define NBW (DD * DD / 4 / 256)     // 1024 blocks per weight
__global__ void convert_all(const float* __restrict__ x,
                            const float* __restrict__ w1,
                            const float* __restrict__ w2)
{
    int blk = blockIdx.x;
    if (blk < NBX) {
        int i = blk * 256 + threadIdx.x;
        float4 v = ((const float4*)x)[i];
        __half2 h01 = __floats2half2_rn(v.x, v.y);
        __half2 h23 = __floats2half2_rn(v.z, v.w);
        __half2 l01 = __floats2half2_rn(v.x - __low2float(h01),
                                        v.y - __high2float(h01));
        __half2 l23 = __floats2half2_rn(v.z - __low2float(h23),
                                        v.w - __high2float(h23));
        ((__half2*)g_xh)[2 * i + 0] = h01;
        ((__half2*)g_xh)[2 * i + 1] = h23;
        ((__half2*)g_xl)[2 * i + 0] = l01;
        ((__half2*)g_xl)[2 * i + 1] = l23;
    } else {
        const float* src = (blk < NBX + NBW) ? w1 : w2;
        __half* hp = (blk < NBX + NBW) ? g_wh1 : g_wh2;
        int i = ((blk < NBX + NBW) ? (blk - NBX) : (blk - NBX - NBW)) * 256 + threadIdx.x;
        float4 v = ((const float4*)src)[i];
        ((__half2*)hp)[2 * i + 0] = __floats2half2_rn(v.x, v.y);
        ((__half2*)hp)[2 * i + 1] = __floats2half2_rn(v.z, v.w);
    }
}

// ---------------------------------------------------------------------------
// mma.sync GEMM: C[n,m] = sum_d A[n,d]*W[m,d] via 2-pass fp16 split
// (D = A_hi*B + A_lo*B, B single fp16; dropped term A*(B-fp16(B)) ~1e-4 rel).
// 128x128 tile, BK=32, 128 threads (4 warps, warp tile 64x64), 2-stage
// cp.async pipeline, 2 CTAs/SM.  (R7/R10 structure — proven best.)
//   MODE 0: A = x(hi/lo),   epi: * cos(freq[m]*pi) -> g_heads, + colsum->g_part
//   MODE 1: A = mixed(hi/lo), epi: + out_b[m] + x[n,m]        -> g_heads
// SMEM rows padded to 80B -> conflict-free ldmatrix phases.
// ---------------------------------------------------------------------------
#define RSB   80                 // row stride bytes (32 fp16 + 16B pad)
#define OPB   (128 * RSB)        // 10240 bytes per operand tile
#define STGB  (3 * OPB)          // 30720 bytes per stage (Ah|Al|Bh)
#define NSTG  2
#define GEMM_SMEM (NSTG * STGB)  // 61440

template<int MODE>
__global__ __launch_bounds__(128, 2)
void gemm_mma(const float* __restrict__ xres, const float* __restrict__ aux)
{
    extern __shared__ char sm[];
    const uint32_t sb = smem_to_u32(sm);
    const int tid = threadIdx.x;
    const int lane = tid & 31;
    const int wid = tid >> 5;        // 0..3
    const int wm = wid & 1;          // 2 M groups of 64
    const int wn = wid >> 1;         // 2 N groups of 64
    const int bc = blockIdx.x;       // col tile 0..7
    const int br = blockIdx.y;       // row tile 0..127

    const __half* Ah = (MODE == 0) ? g_xh : g_mh;
    const __half* Al = (MODE == 0) ? g_xl : g_ml;
    const __half* Bh = (MODE == 0) ? g_wh1 : g_wh2;

    // ---- loader mapping: 12 x 16B per thread per stage ----
    const int r4  = tid >> 2;       // 0..31
    const int seg = tid & 3;        // 16B segment (64B of payload per row)
    const __half* gbase[3];
    gbase[0] = Ah + (size_t)(br * 128 + r4) * DD + seg * 8;
    gbase[1] = Al + (size_t)(br * 128 + r4) * DD + seg * 8;
    gbase[2] = Bh + (size_t)(bc * 128 + r4) * DD + seg * 8;
    const uint32_t sload = sb + r4 * RSB + seg * 16;

    // ---- ldmatrix source offsets (within a stage) ----
    const uint32_t aoff = (uint32_t)((wm * 64 + (lane & 15)) * RSB + (lane >> 4) * 16);
    const uint32_t boff = (uint32_t)((wn * 64 + ((lane >> 4) << 3) + (lane & 7)) * RSB
                                     + ((lane >> 3) & 1) * 16);

    float acc[4][8][4];
#pragma unroll
    for (int i = 0; i < 4; i++)
#pragma unroll
        for (int j = 0; j < 8; j++)
#pragma unroll
            for (int q = 0; q < 4; q++) acc[i][j][q] = 0.f;

    // ---- prologue: fill 2 stages ----
#pragma unroll
    for (int s = 0; s < NSTG; s++) {
#pragma unroll
        for (int op = 0; op < 3; op++)
#pragma unroll
            for (int h = 0; h < 4; h++)
                cpasync16(sload + s * STGB + op * OPB + h * (32 * RSB),
                          gbase[op] + (size_t)h * 32 * DD + s * 32);
        CP_COMMIT();
    }

    // ---- main loop over 32 k-chunks ----
    for (int c = 0; c < 32; c++) {
        CP_WAIT1();
        __syncthreads();
        const uint32_t stg = sb + (c & 1) * STGB;

#pragma unroll
        for (int kk = 0; kk < 2; kk++) {
            uint32_t ah[4][4], al[4][4];
#pragma unroll
            for (int mi = 0; mi < 4; mi++) {
                LDSM4(ah[mi], stg + aoff + mi * (16 * RSB) + kk * 32);
                LDSM4(al[mi], stg + OPB + aoff + mi * (16 * RSB) + kk * 32);
            }
#pragma unroll
            for (int g = 0; g < 4; g++) {
                uint32_t bh[4];
                LDSM4(bh, stg + 2 * OPB + boff + g * (16 * RSB) + kk * 32);
#pragma unroll
                for (int mi = 0; mi < 4; mi++)
#pragma unroll
                    for (int nl = 0; nl < 2; nl++) {
                        const int i0 = nl * 2;
                        float* a = acc[mi][g * 2 + nl];
                        mma_fp16(a, ah[mi], bh[i0], bh[i0 + 1]);
                        mma_fp16(a, al[mi], bh[i0], bh[i0 + 1]);
                    }
            }
        }
        __syncthreads();
        if (c + NSTG < 32) {
            const uint32_t dst = sload + (c & 1) * STGB;
#pragma unroll
            for (int op = 0; op < 3; op++)
#pragma unroll
                for (int h = 0; h < 4; h++)
                    cpasync16(dst + op * OPB + h * (32 * RSB),
                              gbase[op] + (size_t)h * 32 * DD + (c + NSTG) * 32);
        }
        CP_COMMIT();
    }

    // ---- epilogue: fused scale / bias+residual, direct stores ----
    const int mbase = br * 128 + wm * 64;
    const int nbase = bc * 128 + wn * 64;
    const int rq = lane >> 2;
    const int cq = (lane & 3) * 2;
    float csum[8][2];   // MODE 0 only: per-thread column partial sums
#pragma unroll
    for (int ni = 0; ni < 8; ni++) { csum[ni][0] = 0.f; csum[ni][1] = 0.f; }

#pragma unroll
    for (int ni = 0; ni < 8; ni++) {
        const int col = nbase + ni * 8 + cq;
        float f0, f1;
        if (MODE == 0) {
            f0 = cosf(aux[col] * PI_F);
            f1 = cosf(aux[col + 1] * PI_F);
        } else {
            f0 = aux[col];
            f1 = aux[col + 1];
        }
#pragma unroll
        for (int mi = 0; mi < 4; mi++) {
            const int r0 = mbase + mi * 16 + rq;
            float* p0 = g_heads + (size_t)r0 * DD + col;
            float* p1 = g_heads + (size_t)(r0 + 8) * DD + col;
            float2 o0, o1;
            if (MODE == 0) {
                o0.x = acc[mi][ni][0] * f0; o0.y = acc[mi][ni][1] * f1;
                o1.x = acc[mi][ni][2] * f0; o1.y = acc[mi][ni][3] * f1;
                csum[ni][0] += o0.x + o1.x;
                csum[ni][1] += o0.y + o1.y;
            } else {
                float2 x0 = *(const float2*)(xres + (size_t)r0 * DD + col);
                float2 x1 = *(const float2*)(xres + (size_t)(r0 + 8) * DD + col);
                o0.x = acc[mi][ni][0] + f0 + x0.x; o0.y = acc[mi][ni][1] + f1 + x0.y;
                o1.x = acc[mi][ni][2] + f0 + x1.x; o1.y = acc[mi][ni][3] + f1 + x1.y;
            }
            *(float2*)p0 = o0;
            *(float2*)p1 = o1;
        }
    }

    if (MODE == 0) {
        // deterministic colsum: shfl over rq lanes; smem accumulate with
        // exactly 2 commutative adds per slot; write per-row-tile partial.
        float* scs = (float*)sm;   // stages dead (mainloop ended with sync)
        scs[tid] = 0.f;
        __syncthreads();
#pragma unroll
        for (int ni = 0; ni < 8; ni++) {
            float v0 = csum[ni][0], v1 = csum[ni][1];
#pragma unroll
            for (int o = 4; o < 32; o <<= 1) {
                v0 += __shfl_xor_sync(0xffffffffu, v0, o);
                v1 += __shfl_xor_sync(0xffffffffu, v1, o);
            }
            if (rq == 0) {
                atomicAdd(&scs[wn * 64 + ni * 8 + cq], v0);
                atomicAdd(&scs[wn * 64 + ni * 8 + cq + 1], v1);
            }
        }
        __syncthreads();
        g_part[(size_t)br * DD + bc * 128 + tid] = scs[tid];
    }
}

// ---------------------------------------------------------------------------
// Fused summary-reduce + polarity + impedance.  grid=BB, 1024 threads.
// ---------------------------------------------------------------------------
__global__ void polarity_fused(const float* __restrict__ pol_W,
                               const float* __restrict__ pol_b,
                               const float* __restrict__ W1,
                               const float* __restrict__ b1,
                               const float* __restrict__ W2,
                               const float* __restrict__ b2,
                               float* __restrict__ imp_out)
{
    const int b = blockIdx.x;
    const int tid = threadIdx.x;
    __shared__ float s_sum[DD];
    __shared__ float s_pol[HH * PP];

    // summary for batch b: fixed-order sum of its 32 row-tile partials
    float s = 0.f;
#pragma unroll 8
    for (int c = 0; c < 32; c++)
        s += g_part[(size_t)(b * 32 + c) * DD + tid];
    s_sum[tid] = s * (1.0f / (float)SS);
    __syncthreads();

    // dot: tid = h*128 + p*4 + q ; 4 lanes per (h,p), 32 k each
    const int h = tid >> 7;
    const int p = (tid >> 2) & 31;
    const int q = tid & 3;
    const float4* pw = (const float4*)(pol_W + (size_t)(h * PP + p) * KK + q * 32);
    const float* xs = s_sum + h * KK + q * 32;
    float acc = 0.f;
#pragma unroll
    for (int k4 = 0; k4 < 8; k4++) {
        float4 w = pw[k4];
        acc += xs[k4 * 4 + 0] * w.x + xs[k4 * 4 + 1] * w.y
             + xs[k4 * 4 + 2] * w.z + xs[k4 * 4 + 3] * w.w;
    }
    acc += __shfl_xor_sync(0xffffffffu, acc, 1);
    acc += __shfl_xor_sync(0xffffffffu, acc, 2);
    if (q == 0) s_pol[h * PP + p] = tanhf(acc + pol_b[h * PP + p]);
    __syncthreads();

    // normalize: warp w = head w
    const int wid = tid >> 5, lane = tid & 31;
    if (wid < HH) {
        float pv = s_pol[wid * PP + lane];
        float ss2 = pv * pv;
#pragma unroll
        for (int o = 16; o; o >>= 1) ss2 += __shfl_xor_sync(0xffffffffu, ss2, o);
        s_pol[wid * PP + lane] = pv / fmaxf(sqrtf(ss2), 1e-12f);
    }
    __syncthreads();

    // impedance: 64 (i,j) pairs
    if (tid < HH * HH) {
        const int i = tid >> 3;
        const int j = tid & 7;
        float d = 0.f;
#pragma unroll
        for (int pp = 0; pp < PP; pp++) d += s_pol[i * PP + pp] * s_pol[j * PP + pp];

        float sum2 = b2[0];
#pragma unroll
        for (int c = 0; c < 16; c++) {
            float z = d * W1[c] + b1[c];
            float g = 0.5f * z * (1.f + erff(z * 0.70710678118654752f));
            sum2 += g * W2[c];
        }
        float imp = (sum2 > 0.f) ? sum2 + log1pf(expf(-sum2)) : log1pf(expf(sum2));
        if (i == j) imp = 0.f;
        imp_out[b * 64 + tid] = imp;
        g_coef[b * 64 + tid] = (i == j) ? 0.f : 0.1f / (1.f + imp);
    }
}

// ---------------------------------------------------------------------------
// Cross-head mixing with causal scale -> fp16 hi/lo (GEMM2 A operand)
// ---------------------------------------------------------------------------
__global__ void mixing_kernel(const int* __restrict__ causal)
{
    const int bs = blockIdx.x;          // 0..16383
    const int b = bs >> 12;
    const int s = bs & (SS - 1);
    const int k = threadIdx.x;          // 0..127
    __shared__ float sc[HH * HH];
    if (threadIdx.x < HH * HH) sc[threadIdx.x] = g_coef[b * 64 + threadIdx.x];
    __syncthreads();

    const float* row = g_heads + (size_t)bs * DD;
    float v[HH];
#pragma unroll
    for (int j = 0; j < HH; j++) v[j] = row[j * KK + k];

    const float scale = (*causal) ? (float)(s + 1) * (1.0f / (float)SS) : 1.0f;

    __half* oh = g_mh + (size_t)bs * DD;
    __half* ol = g_ml + (size_t)bs * DD;
#pragma unroll
    for (int i = 0; i < HH; i++) {
        float t = 0.f;
#pragma unroll
        for (int j = 0; j < HH; j++) t += sc[i * 8 + j] * v[j];
        float val = v[i] + scale * t;
        __half h = __float2half_rn(val);
        oh[i * KK + k] = h;
        ol[i * KK + k] = __float2half_rn(val - __half2float(h));
    }
}

// ---------------------------------------------------------------------------
// LayerNorm over D (y lives in g_heads after GEMM2)
// ---------------------------------------------------------------------------
__global__ void layernorm_kernel(const float* __restrict__ gamma,
                                 const float* __restrict__ beta,
                                 float* __restrict__ out)
{
    const int row = blockIdx.x;
    const int t = threadIdx.x;          // 0..255
    const float4 v = ((const float4*)(g_heads + (size_t)row * DD))[t];
    float s  = v.x + v.y + v.z + v.w;
    float s2 = v.x * v.x + v.y * v.y + v.z * v.z + v.w * v.w;

#pragma unroll
    for (int o = 16; o; o >>= 1) {
        s  += __shfl_xor_sync(0xffffffffu, s, o);
        s2 += __shfl_xor_sync(0xffffffffu, s2, o);
    }
    __shared__ float sh[8], sh2[8];
    const int w = t >> 5, lane = t & 31;
    if (lane == 0) { sh[w] = s; sh2[w] = s2; }
    __syncthreads();
    if (w == 0) {
        s  = (lane < 8) ? sh[lane]  : 0.f;
        s2 = (lane < 8) ? sh2[lane] : 0.f;
#pragma unroll
        for (int o = 4; o; o >>= 1) {
            s  += __shfl_xor_sync(0xffffffffu, s, o);
            s2 += __shfl_xor_sync(0xffffffffu, s2, o);
        }
        if (lane == 0) { sh[0] = s; sh2[0] = s2; }
    }
    __syncthreads();
    const float mu  = sh[0] * (1.f / (float)DD);
    const float var = sh2[0] * (1.f / (float)DD) - mu * mu;
    const float inv = rsqrtf(var + 1e-5f);

    const float4 g4 = ((const float4*)gamma)[t];
    const float4 b4 = ((const float4*)beta)[t];
    float4 o4;
    o4.x = (v.x - mu) * inv * g4.x + b4.x;
    o4.y = (v.y - mu) * inv * g4.y + b4.y;
    o4.z = (v.z - mu) * inv * g4.z + b4.z;
    o4.w = (v.w - mu) * inv * g4.w + b4.w;
    ((float4*)(out + (size_t)row * DD))[t] = o4;
}

// ---------------------------------------------------------------------------
extern "C" void kernel_launch(void* const* d_in, const int* in_sizes, int n_in,
                              void* d_out, int out_size)
{
    const float* x      = (const float*)d_in[0];   // (B,S,D)
    const float* W_proj = (const float*)d_in[1];   // (H,K,D) -> (1024,1024)
    const float* freqs  = (const float*)d_in[2];   // (H,K) -> 1024
    const float* pol_W  = (const float*)d_in[3];
    const float* pol_b  = (const float*)d_in[4];
    const float* imp_W1 = (const float*)d_in[5];
    const float* imp_b1 = (const float*)d_in[6];
    const float* imp_W2 = (const float*)d_in[7];
    const float* imp_b2 = (const float*)d_in[8];
    const float* out_W  = (const float*)d_in[9];
    const float* out_b  = (const float*)d_in[10];
    const float* ln_g   = (const float*)d_in[11];
    const float* ln_b   = (const float*)d_in[12];
    const int*   causal = (const int*)d_in[13];

    float* out = (float*)d_out;
    float* imp_out = out + (out_size - BB * HH * HH);  // impedance tail

    cudaFuncSetAttribute(gemm_mma<0>, cudaFuncAttributeMaxDynamicSharedMemorySize, GEMM_SMEM);
    cudaFuncSetAttribute(gemm_mma<1>, cudaFuncAttributeMaxDynamicSharedMemorySize, GEMM_SMEM);

    dim3 ggrid(DD / 128, NROW / 128);  // (8, 128)

    // 0) fp16 conversions: x hi/lo split, weights single (one launch)
    convert_all<<<NBX + 2 * NBW, 256>>>(x, W_proj, out_W);
    // 1) heads = (x @ W_proj^T) * cos(freq*pi) -> g_heads, colsums -> g_part
    gemm_mma<0><<<ggrid, 128, GEMM_SMEM>>>(x, freqs);
    // 2) summary reduce + pol / impedance / coef (fused, one launch)
    polarity_fused<<<BB, 1024>>>(pol_W, pol_b, imp_W1, imp_b1, imp_W2, imp_b2, imp_out);
    // 3) cross-head mixing with causal scale     -> g_mh/g_ml (fp16 split)
    mixing_kernel<<<NROW, 128>>>(causal);
    // 4) y = mixed @ out_W^T + out_b + x         -> g_heads   [mma.sync 2xfp16]
    gemm_mma<1><<<ggrid, 128, GEMM_SMEM>>>(x, out_b);
    // 5) LayerNorm -> d_out
    layernorm_kernel<<<NROW, 256>>>(ln_g, ln_b, out);
}

// round 16
// speedup vs baseline: 2.3368x; 1.5383x over previous
#include <cuda_runtime.h>
#include <cuda_fp16.h>
#include <math.h>
#include <stdint.h>

// Problem constants
#define BB 4
#define SS 4096
#define DD 1024
#define HH 8
#define KK 128
#define PP 32
#define NROW (BB*SS)          // 16384
#define PI_F 3.14159265358979f

// ---------------------------------------------------------------------------
// Device-global scratch (no allocations allowed)
// ---------------------------------------------------------------------------
__device__ __half g_xh[(size_t)NROW * DD];   // fp16 x
__device__ __half g_mh[(size_t)NROW * DD];   // fp16 mixed
__device__ __half g_wh1[DD * DD];            // W_proj fp16
__device__ __half g_wh2[DD * DD];            // out_W fp16
__device__ float g_heads[(size_t)NROW * DD]; // heads fp32, later y
__device__ float g_part[128 * DD];           // per-row-tile column sums
__device__ float g_coef[BB * HH * HH];       // 0.1/(1+imp), zero diag

__device__ __forceinline__ uint32_t smem_to_u32(const void* smem_ptr) {
    uint32_t addr;
    asm("{ .reg .u64 tmp; cvta.to.shared.u64 tmp, %1; cvt.u32.u64 %0, tmp; }"
        : "=r"(addr) : "l"(smem_ptr));
    return addr;
}

__device__ __forceinline__ void cpasync16(uint32_t dst, const void* src) {
    asm volatile("cp.async.cg.shared.global [%0], [%1], 16;"
                 :: "r"(dst), "l"(src) : "memory");
}

#define CP_COMMIT() asm volatile("cp.async.commit_group;" ::: "memory")
#define CP_WAIT2()  asm volatile("cp.async.wait_group 2;" ::: "memory")

#define LDSM4(r, addr) \
    asm volatile("ldmatrix.sync.aligned.m8n8.x4.shared.b16 {%0,%1,%2,%3}, [%4];" \
        : "=r"((r)[0]), "=r"((r)[1]), "=r"((r)[2]), "=r"((r)[3]) : "r"(addr))

__device__ __forceinline__ void mma_fp16(float* c, const uint32_t* a,
                                         uint32_t b0, uint32_t b1) {
    asm volatile(
        "mma.sync.aligned.m16n8k16.row.col.f32.f16.f16.f32 "
        "{%0,%1,%2,%3}, {%4,%5,%6,%7}, {%8,%9}, {%0,%1,%2,%3};"
        : "+f"(c[0]), "+f"(c[1]), "+f"(c[2]), "+f"(c[3])
        : "r"(a[0]), "r"(a[1]), "r"(a[2]), "r"(a[3]), "r"(b0), "r"(b1));
}

// ---------------------------------------------------------------------------
// fp16 conversion: x, W_proj, out_W -> single fp16.  ONE launch.
// ---------------------------------------------------------------------------
#define NBX (NROW * DD / 4 / 256)   // 4096 blocks for x
#define NBW (DD * DD / 4 / 256)     // 1024 blocks per weight
__global__ void convert_all(const float* __restrict__ x,
                            const float* __restrict__ w1,
                            const float* __restrict__ w2)
{
    int blk = blockIdx.x;
    const float* src;
    __half* hp;
    int i;
    if (blk < NBX) {
        src = x;  hp = g_xh;  i = blk * 256 + threadIdx.x;
    } else if (blk < NBX + NBW) {
        src = w1; hp = g_wh1; i = (blk - NBX) * 256 + threadIdx.x;
    } else {
        src = w2; hp = g_wh2; i = (blk - NBX - NBW) * 256 + threadIdx.x;
    }
    float4 v = ((const float4*)src)[i];
    ((__half2*)hp)[2 * i + 0] = __floats2half2_rn(v.x, v.y);
    ((__half2*)hp)[2 * i + 1] = __floats2half2_rn(v.z, v.w);
}

// ---------------------------------------------------------------------------
// mma.sync GEMM: C[n,m] = sum_d A[n,d]*W[m,d], single-pass fp16
// (error ~2.8e-4 rel, calibrated; threshold 1e-3).
// 128x128 tile, BK=32, 128 threads (4 warps, warp tile 64x64), 3-stage
// cp.async pipeline, 2 CTAs/SM.
//   MODE 0: A = x,     epi: * cos(freq[m]*pi) -> g_heads, + colsum -> g_part
//   MODE 1: A = mixed, epi: + out_b[m] + x[n,m]           -> g_heads
// SMEM rows padded to 80B -> conflict-free ldmatrix phases.
// ---------------------------------------------------------------------------
#define RSB   80                 // row stride bytes (32 fp16 + 16B pad)
#define OPB   (128 * RSB)        // 10240 bytes per operand tile
#define STGB  (2 * OPB)          // 20480 bytes per stage (A|B)
#define NSTG  3
#define GEMM_SMEM (NSTG * STGB)  // 61440

template<int MODE>
__global__ __launch_bounds__(128, 2)
void gemm_mma(const float* __restrict__ xres, const float* __restrict__ aux)
{
    extern __shared__ char sm[];
    const uint32_t sb = smem_to_u32(sm);
    const int tid = threadIdx.x;
    const int lane = tid & 31;
    const int wid = tid >> 5;        // 0..3
    const int wm = wid & 1;          // 2 M groups of 64
    const int wn = wid >> 1;         // 2 N groups of 64
    const int bc = blockIdx.x;       // col tile 0..7
    const int br = blockIdx.y;       // row tile 0..127

    const __half* A = (MODE == 0) ? g_xh : g_mh;
    const __half* B = (MODE == 0) ? g_wh1 : g_wh2;

    // ---- loader mapping: 8 x 16B per thread per stage ----
    const int r4  = tid >> 2;       // 0..31
    const int seg = tid & 3;        // 16B segment (64B of payload per row)
    const __half* gbase[2];
    gbase[0] = A + (size_t)(br * 128 + r4) * DD + seg * 8;
    gbase[1] = B + (size_t)(bc * 128 + r4) * DD + seg * 8;
    const uint32_t sload = sb + r4 * RSB + seg * 16;

    // ---- ldmatrix source offsets (within a stage) ----
    const uint32_t aoff = (uint32_t)((wm * 64 + (lane & 15)) * RSB + (lane >> 4) * 16);
    const uint32_t boff = (uint32_t)((wn * 64 + ((lane >> 4) << 3) + (lane & 7)) * RSB
                                     + ((lane >> 3) & 1) * 16);

    float acc[4][8][4];
#pragma unroll
    for (int i = 0; i < 4; i++)
#pragma unroll
        for (int j = 0; j < 8; j++)
#pragma unroll
            for (int q = 0; q < 4; q++) acc[i][j][q] = 0.f;

    // ---- prologue: fill 3 stages ----
#pragma unroll
    for (int s = 0; s < NSTG; s++) {
#pragma unroll
        for (int op = 0; op < 2; op++)
#pragma unroll
            for (int h = 0; h < 4; h++)
                cpasync16(sload + s * STGB + op * OPB + h * (32 * RSB),
                          gbase[op] + (size_t)h * 32 * DD + s * 32);
        CP_COMMIT();
    }

    // ---- main loop over 32 k-chunks ----
    for (int c = 0; c < 32; c++) {
        CP_WAIT2();
        __syncthreads();
        const uint32_t stg = sb + (c % NSTG) * STGB;

#pragma unroll
        for (int kk = 0; kk < 2; kk++) {
            uint32_t ah[4][4];
#pragma unroll
            for (int mi = 0; mi < 4; mi++)
                LDSM4(ah[mi], stg + aoff + mi * (16 * RSB) + kk * 32);
#pragma unroll
            for (int g = 0; g < 4; g++) {
                uint32_t bh[4];
                LDSM4(bh, stg + OPB + boff + g * (16 * RSB) + kk * 32);
#pragma unroll
                for (int mi = 0; mi < 4; mi++)
#pragma unroll
                    for (int nl = 0; nl < 2; nl++) {
                        const int i0 = nl * 2;
                        mma_fp16(acc[mi][g * 2 + nl], ah[mi], bh[i0], bh[i0 + 1]);
                    }
            }
        }
        __syncthreads();
        if (c + NSTG < 32) {
            const uint32_t dst = sload + (c % NSTG) * STGB;
#pragma unroll
            for (int op = 0; op < 2; op++)
#pragma unroll
                for (int h = 0; h < 4; h++)
                    cpasync16(dst + op * OPB + h * (32 * RSB),
                              gbase[op] + (size_t)h * 32 * DD + (c + NSTG) * 32);
        }
        CP_COMMIT();
    }

    // ---- epilogue: fused scale / bias+residual, direct stores ----
    const int mbase = br * 128 + wm * 64;
    const int nbase = bc * 128 + wn * 64;
    const int rq = lane >> 2;
    const int cq = (lane & 3) * 2;
    float csum[8][2];   // MODE 0 only: per-thread column partial sums
#pragma unroll
    for (int ni = 0; ni < 8; ni++) { csum[ni][0] = 0.f; csum[ni][1] = 0.f; }

#pragma unroll
    for (int ni = 0; ni < 8; ni++) {
        const int col = nbase + ni * 8 + cq;
        float f0, f1;
        if (MODE == 0) {
            f0 = cosf(aux[col] * PI_F);
            f1 = cosf(aux[col + 1] * PI_F);
        } else {
            f0 = aux[col];
            f1 = aux[col + 1];
        }
#pragma unroll
        for (int mi = 0; mi < 4; mi++) {
            const int r0 = mbase + mi * 16 + rq;
            float* p0 = g_heads + (size_t)r0 * DD + col;
            float* p1 = g_heads + (size_t)(r0 + 8) * DD + col;
            float2 o0, o1;
            if (MODE == 0) {
                o0.x = acc[mi][ni][0] * f0; o0.y = acc[mi][ni][1] * f1;
                o1.x = acc[mi][ni][2] * f0; o1.y = acc[mi][ni][3] * f1;
                csum[ni][0] += o0.x + o1.x;
                csum[ni][1] += o0.y + o1.y;
            } else {
                float2 x0 = *(const float2*)(xres + (size_t)r0 * DD + col);
                float2 x1 = *(const float2*)(xres + (size_t)(r0 + 8) * DD + col);
                o0.x = acc[mi][ni][0] + f0 + x0.x; o0.y = acc[mi][ni][1] + f1 + x0.y;
                o1.x = acc[mi][ni][2] + f0 + x1.x; o1.y = acc[mi][ni][3] + f1 + x1.y;
            }
            *(float2*)p0 = o0;
            *(float2*)p1 = o1;
        }
    }

    if (MODE == 0) {
        // deterministic colsum: shfl over rq lanes; smem accumulate with
        // exactly 2 commutative adds per slot; write per-row-tile partial.
        float* scs = (float*)sm;   // stages dead (mainloop ended with sync)
        scs[tid] = 0.f;
        __syncthreads();
#pragma unroll
        for (int ni = 0; ni < 8; ni++) {
            float v0 = csum[ni][0], v1 = csum[ni][1];
#pragma unroll
            for (int o = 4; o < 32; o <<= 1) {
                v0 += __shfl_xor_sync(0xffffffffu, v0, o);
                v1 += __shfl_xor_sync(0xffffffffu, v1, o);
            }
            if (rq == 0) {
                atomicAdd(&scs[wn * 64 + ni * 8 + cq], v0);
                atomicAdd(&scs[wn * 64 + ni * 8 + cq + 1], v1);
            }
        }
        __syncthreads();
        g_part[(size_t)br * DD + bc * 128 + tid] = scs[tid];
    }
}

// ---------------------------------------------------------------------------
// Fused summary-reduce + polarity + impedance.  grid=BB, 1024 threads.
// ---------------------------------------------------------------------------
__global__ void polarity_fused(const float* __restrict__ pol_W,
                               const float* __restrict__ pol_b,
                               const float* __restrict__ W1,
                               const float* __restrict__ b1,
                               const float* __restrict__ W2,
                               const float* __restrict__ b2,
                               float* __restrict__ imp_out)
{
    const int b = blockIdx.x;
    const int tid = threadIdx.x;
    __shared__ float s_sum[DD];
    __shared__ float s_pol[HH * PP];

    // summary for batch b: fixed-order sum of its 32 row-tile partials
    float s = 0.f;
#pragma unroll 8
    for (int c = 0; c < 32; c++)
        s += g_part[(size_t)(b * 32 + c) * DD + tid];
    s_sum[tid] = s * (1.0f / (float)SS);
    __syncthreads();

    // dot: tid = h*128 + p*4 + q ; 4 lanes per (h,p), 32 k each
    const int h = tid >> 7;
    const int p = (tid >> 2) & 31;
    const int q = tid & 3;
    const float4* pw = (const float4*)(pol_W + (size_t)(h * PP + p) * KK + q * 32);
    const float* xs = s_sum + h * KK + q * 32;
    float acc = 0.f;
#pragma unroll
    for (int k4 = 0; k4 < 8; k4++) {
        float4 w = pw[k4];
        acc += xs[k4 * 4 + 0] * w.x + xs[k4 * 4 + 1] * w.y
             + xs[k4 * 4 + 2] * w.z + xs[k4 * 4 + 3] * w.w;
    }
    acc += __shfl_xor_sync(0xffffffffu, acc, 1);
    acc += __shfl_xor_sync(0xffffffffu, acc, 2);
    if (q == 0) s_pol[h * PP + p] = tanhf(acc + pol_b[h * PP + p]);
    __syncthreads();

    // normalize: warp w = head w
    const int wid = tid >> 5, lane = tid & 31;
    if (wid < HH) {
        float pv = s_pol[wid * PP + lane];
        float ss2 = pv * pv;
#pragma unroll
        for (int o = 16; o; o >>= 1) ss2 += __shfl_xor_sync(0xffffffffu, ss2, o);
        s_pol[wid * PP + lane] = pv / fmaxf(sqrtf(ss2), 1e-12f);
    }
    __syncthreads();

    // impedance: 64 (i,j) pairs
    if (tid < HH * HH) {
        const int i = tid >> 3;
        const int j = tid & 7;
        float d = 0.f;
#pragma unroll
        for (int pp = 0; pp < PP; pp++) d += s_pol[i * PP + pp] * s_pol[j * PP + pp];

        float sum2 = b2[0];
#pragma unroll
        for (int c = 0; c < 16; c++) {
            float z = d * W1[c] + b1[c];
            float g = 0.5f * z * (1.f + erff(z * 0.70710678118654752f));
            sum2 += g * W2[c];
        }
        float imp = (sum2 > 0.f) ? sum2 + log1pf(expf(-sum2)) : log1pf(expf(sum2));
        if (i == j) imp = 0.f;
        imp_out[b * 64 + tid] = imp;
        g_coef[b * 64 + tid] = (i == j) ? 0.f : 0.1f / (1.f + imp);
    }
}

// ---------------------------------------------------------------------------
// Cross-head mixing with causal scale -> fp16 (GEMM2 A operand)
// ---------------------------------------------------------------------------
__global__ void mixing_kernel(const int* __restrict__ causal)
{
    const int bs = blockIdx.x;          // 0..16383
    const int b = bs >> 12;
    const int s = bs & (SS - 1);
    const int k = threadIdx.x;          // 0..127
    __shared__ float sc[HH * HH];
    if (threadIdx.x < HH * HH) sc[threadIdx.x] = g_coef[b * 64 + threadIdx.x];
    __syncthreads();

    const float* row = g_heads + (size_t)bs * DD;
    float v[HH];
#pragma unroll
    for (int j = 0; j < HH; j++) v[j] = row[j * KK + k];

    const float scale = (*causal) ? (float)(s + 1) * (1.0f / (float)SS) : 1.0f;

    __half* oh = g_mh + (size_t)bs * DD;
#pragma unroll
    for (int i = 0; i < HH; i++) {
        float t = 0.f;
#pragma unroll
        for (int j = 0; j < HH; j++) t += sc[i * 8 + j] * v[j];
        oh[i * KK + k] = __float2half_rn(v[i] + scale * t);
    }
}

// ---------------------------------------------------------------------------
// LayerNorm over D (y lives in g_heads after GEMM2)
// ---------------------------------------------------------------------------
__global__ void layernorm_kernel(const float* __restrict__ gamma,
                                 const float* __restrict__ beta,
                                 float* __restrict__ out)
{
    const int row = blockIdx.x;
    const int t = threadIdx.x;          // 0..255
    const float4 v = ((const float4*)(g_heads + (size_t)row * DD))[t];
    float s  = v.x + v.y + v.z + v.w;
    float s2 = v.x * v.x + v.y * v.y + v.z * v.z + v.w * v.w;

#pragma unroll
    for (int o = 16; o; o >>= 1) {
        s  += __shfl_xor_sync(0xffffffffu, s, o);
        s2 += __shfl_xor_sync(0xffffffffu, s2, o);
    }
    __shared__ float sh[8], sh2[8];
    const int w = t >> 5, lane = t & 31;
    if (lane == 0) { sh[w] = s; sh2[w] = s2; }
    __syncthreads();
    if (w == 0) {
        s  = (lane < 8) ? sh[lane]  : 0.f;
        s2 = (lane < 8) ? sh2[lane] : 0.f;
#pragma unroll
        for (int o = 4; o; o >>= 1) {
            s  += __shfl_xor_sync(0xffffffffu, s, o);
            s2 += __shfl_xor_sync(0xffffffffu, s2, o);
        }
        if (lane == 0) { sh[0] = s; sh2[0] = s2; }
    }
    __syncthreads();
    const float mu  = sh[0] * (1.f / (float)DD);
    const float var = sh2[0] * (1.f / (float)DD) - mu * mu;
    const float inv = rsqrtf(var + 1e-5f);

    const float4 g4 = ((const float4*)gamma)[t];
    const float4 b4 = ((const float4*)beta)[t];
    float4 o4;
    o4.x = (v.x - mu) * inv * g4.x + b4.x;
    o4.y = (v.y - mu) * inv * g4.y + b4.y;
    o4.z = (v.z - mu) * inv * g4.z + b4.z;
    o4.w = (v.w - mu) * inv * g4.w + b4.w;
    ((float4*)(out + (size_t)row * DD))[t] = o4;
}

// ---------------------------------------------------------------------------
extern "C" void kernel_launch(void* const* d_in, const int* in_sizes, int n_in,
                              void* d_out, int out_size)
{
    const float* x      = (const float*)d_in[0];   // (B,S,D)
    const float* W_proj = (const float*)d_in[1];   // (H,K,D) -> (1024,1024)
    const float* freqs  = (const float*)d_in[2];   // (H,K) -> 1024
    const float* pol_W  = (const float*)d_in[3];
    const float* pol_b  = (const float*)d_in[4];
    const float* imp_W1 = (const float*)d_in[5];
    const float* imp_b1 = (const float*)d_in[6];
    const float* imp_W2 = (const float*)d_in[7];
    const float* imp_b2 = (const float*)d_in[8];
    const float* out_W  = (const float*)d_in[9];
    const float* out_b  = (const float*)d_in[10];
    const float* ln_g   = (const float*)d_in[11];
    const float* ln_b   = (const float*)d_in[12];
    const int*   causal = (const int*)d_in[13];

    float* out = (float*)d_out;
    float* imp_out = out + (out_size - BB * HH * HH);  // impedance tail

    cudaFuncSetAttribute(gemm_mma<0>, cudaFuncAttributeMaxDynamicSharedMemorySize, GEMM_SMEM);
    cudaFuncSetAttribute(gemm_mma<1>, cudaFuncAttributeMaxDynamicSharedMemorySize, GEMM_SMEM);

    dim3 ggrid(DD / 128, NROW / 128);  // (8, 128)

    // 0) fp16 conversions: x, W_proj, out_W (one launch)
    convert_all<<<NBX + 2 * NBW, 256>>>(x, W_proj, out_W);
    // 1) heads = (x @ W_proj^T) * cos(freq*pi) -> g_heads, colsums -> g_part
    gemm_mma<0><<<ggrid, 128, GEMM_SMEM>>>(x, freqs);
    // 2) summary reduce + pol / impedance / coef (fused, one launch)
    polarity_fused<<<BB, 1024>>>(pol_W, pol_b, imp_W1, imp_b1, imp_W2, imp_b2, imp_out);
    // 3) cross-head mixing with causal scale     -> g_mh (fp16)
    mixing_kernel<<<NROW, 128>>>(causal);
    // 4) y = mixed @ out_W^T + out_b + x         -> g_heads   [mma.sync fp16]
    gemm_mma<1><<<ggrid, 128, GEMM_SMEM>>>(x, out_b);
    // 5) LayerNorm -> d_out
    layernorm_kernel<<<NROW, 256>>>(ln_g, ln_b, out);
}